// round 1
// baseline (speedup 1.0000x reference)
#include <cuda_runtime.h>
#include <cstdint>
#include <cstddef>

#define B_SZ    2
#define SEQ_N   2048
#define SEQ_M   2048
#define DIM_C   1024
#define HEADS   16
#define HEAD_D  64

// Scratch (allocation-free rule: __device__ globals)
__device__ float g_Q[(size_t)B_SZ * SEQ_N * DIM_C];
__device__ float g_K[(size_t)B_SZ * SEQ_M * DIM_C];
__device__ float g_O[(size_t)B_SZ * SEQ_N * DIM_C];

// ---------------------------------------------------------------------------
// GEMM  C[M,N] = alpha * A[M,K] @ B[N,K]^T (+ bias[N])
// A row-major (K contiguous), B row-major (K contiguous)  -> "NT" gemm.
// Tiles: 128x128x16, 256 threads, 8x8 register tile per thread.
// ---------------------------------------------------------------------------
__global__ __launch_bounds__(256, 2) void gemm_nt_kernel(
    const float* __restrict__ A, const float* __restrict__ B,
    float* __restrict__ C, const float* __restrict__ bias,
    int M, int N, int K, float alpha)
{
    __shared__ float As[16][128];
    __shared__ float Bs[16][128];

    const int tid = threadIdx.x;
    const int tx  = tid & 15;     // n direction
    const int ty  = tid >> 4;     // m direction
    const int m0  = blockIdx.y * 128;
    const int n0  = blockIdx.x * 128;

    const float* Ab = A + (size_t)m0 * K;
    const float* Bb = B + (size_t)n0 * K;

    float acc[8][8];
#pragma unroll
    for (int i = 0; i < 8; i++)
#pragma unroll
        for (int j = 0; j < 8; j++) acc[i][j] = 0.f;

    for (int kt = 0; kt < K; kt += 16) {
        // 128x16 tiles: 512 float4 slots per matrix, 2 per thread each.
#pragma unroll
        for (int u = 0; u < 2; u++) {
            int s   = tid + u * 256;
            int row = s >> 2;            // 0..127
            int k4  = (s & 3) << 2;      // 0,4,8,12
            float4 av = *(const float4*)(Ab + (size_t)row * K + kt + k4);
            float4 bv = *(const float4*)(Bb + (size_t)row * K + kt + k4);
            As[k4 + 0][row] = av.x; As[k4 + 1][row] = av.y;
            As[k4 + 2][row] = av.z; As[k4 + 3][row] = av.w;
            Bs[k4 + 0][row] = bv.x; Bs[k4 + 1][row] = bv.y;
            Bs[k4 + 2][row] = bv.z; Bs[k4 + 3][row] = bv.w;
        }
        __syncthreads();

#pragma unroll
        for (int k = 0; k < 16; k++) {
            float a[8], b[8];
            *(float4*)(a)     = *(const float4*)&As[k][ty * 8];
            *(float4*)(a + 4) = *(const float4*)&As[k][ty * 8 + 4];
            *(float4*)(b)     = *(const float4*)&Bs[k][tx * 8];
            *(float4*)(b + 4) = *(const float4*)&Bs[k][tx * 8 + 4];
#pragma unroll
            for (int i = 0; i < 8; i++)
#pragma unroll
                for (int j = 0; j < 8; j++)
                    acc[i][j] += a[i] * b[j];
        }
        __syncthreads();
    }

#pragma unroll
    for (int i = 0; i < 8; i++) {
        size_t rowoff = (size_t)(m0 + ty * 8 + i) * N + n0 + tx * 8;
#pragma unroll
        for (int j = 0; j < 8; j++) {
            float v = alpha * acc[i][j];
            if (bias) v += bias[n0 + tx * 8 + j];
            C[rowoff + j] = v;
        }
    }
}

// ---------------------------------------------------------------------------
// Flash attention, fp32, online softmax. V == K (reference uses kv[:,:,0] for
// both), so the K tile in smem is reused as the V tile: no V loads at all.
// BM=128 query rows / block, BN=64 keys / iter, D=64.
// Thread layout 16x16; S-tile per thread: 8 rows x 4 cols. O acc 8x4.
// ---------------------------------------------------------------------------
#define FBM 128
#define FBN 64
#define FPAD 65

__global__ __launch_bounds__(256, 2) void flash_kernel(
    const float* __restrict__ Q, const float* __restrict__ K,
    float* __restrict__ O)
{
    extern __shared__ float sm[];
    float* Qs = sm;                       // [FBM][FPAD]
    float* Ks = Qs + FBM * FPAD;          // [FBN][FPAD]
    float* Ps = Ks + FBN * FPAD;          // [FBM][FPAD]

    const int tid = threadIdx.x;
    const int tx  = tid & 15;
    const int ty  = tid >> 4;
    const int bh  = blockIdx.y;
    const int b   = bh >> 4;
    const int h   = bh & 15;
    const int q0  = blockIdx.x * FBM;

    const float* Qbase = Q + (((size_t)(b * SEQ_N + q0)) * HEADS + h) * HEAD_D;
    const float* Kbase = K + (((size_t)(b * SEQ_M))      * HEADS + h) * HEAD_D;

    // Load Q tile (128 x 64), row stride in gmem = DIM_C
    for (int s = tid; s < FBM * 16; s += 256) {
        int row = s >> 4;
        int c4  = (s & 15) << 2;
        float4 v = *(const float4*)(Qbase + (size_t)row * DIM_C + c4);
        float* dst = Qs + row * FPAD + c4;
        dst[0] = v.x; dst[1] = v.y; dst[2] = v.z; dst[3] = v.w;
    }

    float m_i[8], l_i[8], acc[8][4];
#pragma unroll
    for (int i = 0; i < 8; i++) {
        m_i[i] = -1e30f; l_i[i] = 0.f;
#pragma unroll
        for (int j = 0; j < 4; j++) acc[i][j] = 0.f;
    }

    for (int kt = 0; kt < SEQ_M; kt += FBN) {
        __syncthreads();   // prior PV done with Ks/Ps; Qs visible (1st iter)
        for (int s = tid; s < FBN * 16; s += 256) {
            int row = s >> 4;
            int c4  = (s & 15) << 2;
            float4 v = *(const float4*)(Kbase + (size_t)(kt + row) * DIM_C + c4);
            float* dst = Ks + row * FPAD + c4;
            dst[0] = v.x; dst[1] = v.y; dst[2] = v.z; dst[3] = v.w;
        }
        __syncthreads();

        // S = Q @ K^T   (scale already folded into Q)
        float sacc[8][4];
#pragma unroll
        for (int i = 0; i < 8; i++)
#pragma unroll
            for (int j = 0; j < 4; j++) sacc[i][j] = 0.f;

#pragma unroll 8
        for (int d = 0; d < HEAD_D; d++) {
            float a[8], bk[4];
#pragma unroll
            for (int i = 0; i < 8; i++) a[i] = Qs[(ty * 8 + i) * FPAD + d];
#pragma unroll
            for (int j = 0; j < 4; j++) bk[j] = Ks[(tx * 4 + j) * FPAD + d];
#pragma unroll
            for (int i = 0; i < 8; i++)
#pragma unroll
                for (int j = 0; j < 4; j++)
                    sacc[i][j] += a[i] * bk[j];
        }

        // Online softmax update
#pragma unroll
        for (int i = 0; i < 8; i++) {
            float mj = fmaxf(fmaxf(sacc[i][0], sacc[i][1]),
                             fmaxf(sacc[i][2], sacc[i][3]));
#pragma unroll
            for (int off = 8; off; off >>= 1)
                mj = fmaxf(mj, __shfl_xor_sync(0xffffffffu, mj, off));
            float mnew = fmaxf(m_i[i], mj);
            float corr = __expf(m_i[i] - mnew);
            float rs = 0.f;
#pragma unroll
            for (int j = 0; j < 4; j++) {
                float p = __expf(sacc[i][j] - mnew);
                Ps[(ty * 8 + i) * FPAD + tx * 4 + j] = p;
                rs += p;
            }
#pragma unroll
            for (int off = 8; off; off >>= 1)
                rs += __shfl_xor_sync(0xffffffffu, rs, off);
            l_i[i] = l_i[i] * corr + rs;
            m_i[i] = mnew;
#pragma unroll
            for (int j = 0; j < 4; j++) acc[i][j] *= corr;
        }
        __syncthreads();   // Ps fully written

        // O += P @ V   with V tile == K tile (Ks[key][d])
#pragma unroll 8
        for (int kk = 0; kk < FBN; kk++) {
            float p[8], vv[4];
#pragma unroll
            for (int i = 0; i < 8; i++) p[i] = Ps[(ty * 8 + i) * FPAD + kk];
#pragma unroll
            for (int j = 0; j < 4; j++) vv[j] = Ks[kk * FPAD + tx * 4 + j];
#pragma unroll
            for (int i = 0; i < 8; i++)
#pragma unroll
                for (int j = 0; j < 4; j++)
                    acc[i][j] += p[i] * vv[j];
        }
    }

    float* Obase = O + (((size_t)(b * SEQ_N + q0)) * HEADS + h) * HEAD_D;
#pragma unroll
    for (int i = 0; i < 8; i++) {
        float inv = 1.f / l_i[i];
#pragma unroll
        for (int j = 0; j < 4; j++)
            Obase[(size_t)(ty * 8 + i) * DIM_C + tx * 4 + j] = acc[i][j] * inv;
    }
}

// ---------------------------------------------------------------------------
extern "C" void kernel_launch(void* const* d_in, const int* in_sizes, int n_in,
                              void* d_out, int out_size)
{
    const float* x      = (const float*)d_in[0];
    const float* ctx    = (const float*)d_in[1];
    const float* W_q    = (const float*)d_in[2];
    const float* W_kv   = (const float*)d_in[3];
    const float* W_proj = (const float*)d_in[4];
    const float* b_proj = (const float*)d_in[5];
    float* out = (float*)d_out;

    float *Qb, *Kb, *Ob;
    cudaGetSymbolAddress((void**)&Qb, g_Q);
    cudaGetSymbolAddress((void**)&Kb, g_K);
    cudaGetSymbolAddress((void**)&Ob, g_O);

    const int Mrows = B_SZ * SEQ_N;          // 4096
    dim3 gemm_grid(DIM_C / 128, Mrows / 128);  // (8, 32)

    // Q = x @ W_q^T * scale   (scale = 1/sqrt(64) = 0.125)
    gemm_nt_kernel<<<gemm_grid, 256>>>(x, W_q, Qb, nullptr,
                                       Mrows, DIM_C, DIM_C, 0.125f);
    // K = context @ W_k^T  (W_k = first 1024 rows of W_kv; V == K)
    gemm_nt_kernel<<<gemm_grid, 256>>>(ctx, W_kv, Kb, nullptr,
                                       Mrows, DIM_C, DIM_C, 1.0f);

    const int fsmem = (FBM + FBN + FBM) * FPAD * (int)sizeof(float); // 83200
    cudaFuncSetAttribute(flash_kernel,
                         cudaFuncAttributeMaxDynamicSharedMemorySize, fsmem);
    flash_kernel<<<dim3(SEQ_N / FBM, B_SZ * HEADS), 256, fsmem>>>(Qb, Kb, Ob);

    // out = O @ W_proj^T + b_proj
    gemm_nt_kernel<<<gemm_grid, 256>>>(Ob, W_proj, out, b_proj,
                                       Mrows, DIM_C, DIM_C, 1.0f);
}

// round 3
// speedup vs baseline: 4.5498x; 4.5498x over previous
#include <cuda_runtime.h>
#include <cuda_fp16.h>
#include <cstdint>
#include <cstddef>

#define B_SZ    2
#define SEQ_N   2048
#define SEQ_M   2048
#define DIM_C   1024
#define HEADS   16
#define HEAD_D  64

// Scratch (allocation-free rule: __device__ globals)
__device__ __half g_Q[(size_t)B_SZ * SEQ_N * DIM_C];
__device__ __half g_K[(size_t)B_SZ * SEQ_M * DIM_C];
__device__ float  g_O[(size_t)B_SZ * SEQ_N * DIM_C];

// ===========================================================================
// helpers
// ===========================================================================
__device__ __forceinline__ uint32_t smem_u32(const void* p) {
    uint32_t a;
    asm("{ .reg .u64 t; cvta.to.shared.u64 t, %1; cvt.u32.u64 %0, t; }"
        : "=r"(a) : "l"(p));
    return a;
}
__device__ __forceinline__ uint32_t f32_tf32(float x) {
    uint32_t u;
    asm("cvt.rna.tf32.f32 %0, %1;" : "=r"(u) : "f"(x));
    return u;
}
__device__ __forceinline__ void mma_tf32(float c[4], const uint32_t a[4],
                                         const uint32_t b[2]) {
    asm volatile(
        "mma.sync.aligned.m16n8k8.row.col.f32.tf32.tf32.f32 "
        "{%0,%1,%2,%3}, {%4,%5,%6,%7}, {%8,%9}, {%0,%1,%2,%3};"
        : "+f"(c[0]), "+f"(c[1]), "+f"(c[2]), "+f"(c[3])
        : "r"(a[0]), "r"(a[1]), "r"(a[2]), "r"(a[3]), "r"(b[0]), "r"(b[1]));
}
__device__ __forceinline__ void mma_f16(float c[4], uint32_t a0, uint32_t a1,
                                        uint32_t a2, uint32_t a3,
                                        uint32_t b0, uint32_t b1) {
    asm volatile(
        "mma.sync.aligned.m16n8k16.row.col.f32.f16.f16.f32 "
        "{%0,%1,%2,%3}, {%4,%5,%6,%7}, {%8,%9}, {%0,%1,%2,%3};"
        : "+f"(c[0]), "+f"(c[1]), "+f"(c[2]), "+f"(c[3])
        : "r"(a0), "r"(a1), "r"(a2), "r"(a3), "r"(b0), "r"(b1));
}
#define LDSM_X4(r0, r1, r2, r3, addr)                                          \
    asm volatile("ldmatrix.sync.aligned.m8n8.x4.shared.b16 {%0,%1,%2,%3}, [%4];" \
                 : "=r"(r0), "=r"(r1), "=r"(r2), "=r"(r3) : "r"(addr))
#define LDSM_X4T(r0, r1, r2, r3, addr)                                         \
    asm volatile("ldmatrix.sync.aligned.m8n8.x4.trans.shared.b16 {%0,%1,%2,%3}, [%4];" \
                 : "=r"(r0), "=r"(r1), "=r"(r2), "=r"(r3) : "r"(addr))
__device__ __forceinline__ void cp_async16(uint32_t dst, const void* src) {
    size_t g = __cvta_generic_to_global(src);
    asm volatile("cp.async.cg.shared.global [%0], [%1], 16;"
                 :: "r"(dst), "l"(g) : "memory");
}
#define CP_COMMIT() asm volatile("cp.async.commit_group;" ::: "memory")
#define CP_WAIT0()  asm volatile("cp.async.wait_group 0;" ::: "memory")

// ===========================================================================
// GEMM  C[M,N] = alpha * A[M,K] @ B[N,K]^T (+ bias), tensor cores (tf32 mma).
// CTA 128x128, 8 warps (2x4), warp tile 64x32, K-chunk 32, 2-stage smem.
// OUT_HALF: write __half (for Q/K feeding fp16 attention), else float.
// ===========================================================================
#define GPAD 36

template <bool OUT_HALF>
__global__ __launch_bounds__(256) void gemm_mma(
    const float* __restrict__ A, const float* __restrict__ B,
    void* __restrict__ Cout, const float* __restrict__ bias,
    int M, int N, int K, float alpha)
{
    extern __shared__ __align__(16) float smg[];
    float* As = smg;                     // [2][128][GPAD]
    float* Bs = smg + 2 * 128 * GPAD;    // [2][128][GPAD]

    const int tid  = threadIdx.x;
    const int lane = tid & 31;
    const int wid  = tid >> 5;
    const int lr   = lane >> 2, lc = lane & 3;
    const int mbase = (wid >> 2) * 64;
    const int nbase = (wid & 3) * 32;
    const int m0 = blockIdx.y * 128, n0 = blockIdx.x * 128;
    const int row0 = tid >> 3, q = tid & 7;

    const float* Ag = A + (size_t)(m0 + row0) * K + q * 4;
    const float* Bg = B + (size_t)(n0 + row0) * K + q * 4;

    float c[4][4][4];
#pragma unroll
    for (int mt = 0; mt < 4; mt++)
#pragma unroll
        for (int nt = 0; nt < 4; nt++)
#pragma unroll
            for (int r = 0; r < 4; r++) c[mt][nt][r] = 0.f;

    float4 av[4], bv[4];
    const int nch = K >> 5;

    // LDG chunk 0
#pragma unroll
    for (int p = 0; p < 4; p++) {
        av[p] = *(const float4*)(Ag + (size_t)(p * 32) * K);
        bv[p] = *(const float4*)(Bg + (size_t)(p * 32) * K);
    }
    // STS chunk 0 -> stage 0
#pragma unroll
    for (int p = 0; p < 4; p++) {
        uint32_t* d = (uint32_t*)&As[(size_t)(row0 + 32 * p) * GPAD + q * 4];
        d[0] = f32_tf32(av[p].x); d[1] = f32_tf32(av[p].y);
        d[2] = f32_tf32(av[p].z); d[3] = f32_tf32(av[p].w);
        uint32_t* e = (uint32_t*)&Bs[(size_t)(row0 + 32 * p) * GPAD + q * 4];
        e[0] = f32_tf32(bv[p].x); e[1] = f32_tf32(bv[p].y);
        e[2] = f32_tf32(bv[p].z); e[3] = f32_tf32(bv[p].w);
    }

    for (int i = 0; i < nch; i++) {
        const int s = i & 1;
        __syncthreads();
        if (i + 1 < nch) {
            const float* Ag2 = Ag + (i + 1) * 32;
            const float* Bg2 = Bg + (i + 1) * 32;
#pragma unroll
            for (int p = 0; p < 4; p++) {
                av[p] = *(const float4*)(Ag2 + (size_t)(p * 32) * K);
                bv[p] = *(const float4*)(Bg2 + (size_t)(p * 32) * K);
            }
        }
        // compute on stage s
        const uint32_t* Ab = (const uint32_t*)(As + (size_t)s * 128 * GPAD);
        const uint32_t* Bb = (const uint32_t*)(Bs + (size_t)s * 128 * GPAD);
#pragma unroll
        for (int ks = 0; ks < 4; ks++) {
            uint32_t af[4][4], bf[4][2];
#pragma unroll
            for (int mt = 0; mt < 4; mt++) {
                int r = (mbase + mt * 16 + lr) * GPAD + ks * 8 + lc;
                af[mt][0] = Ab[r];
                af[mt][1] = Ab[r + 8 * GPAD];
                af[mt][2] = Ab[r + 4];
                af[mt][3] = Ab[r + 8 * GPAD + 4];
            }
#pragma unroll
            for (int nt = 0; nt < 4; nt++) {
                int r = (nbase + nt * 8 + lr) * GPAD + ks * 8 + lc;
                bf[nt][0] = Bb[r];
                bf[nt][1] = Bb[r + 4];
            }
#pragma unroll
            for (int mt = 0; mt < 4; mt++)
#pragma unroll
                for (int nt = 0; nt < 4; nt++)
                    mma_tf32(c[mt][nt], af[mt], bf[nt]);
        }
        if (i + 1 < nch) {
            __syncthreads();
            const int t = s ^ 1;
#pragma unroll
            for (int p = 0; p < 4; p++) {
                uint32_t* d = (uint32_t*)&As[(size_t)(t * 128 + row0 + 32 * p) * GPAD + q * 4];
                d[0] = f32_tf32(av[p].x); d[1] = f32_tf32(av[p].y);
                d[2] = f32_tf32(av[p].z); d[3] = f32_tf32(av[p].w);
                uint32_t* e = (uint32_t*)&Bs[(size_t)(t * 128 + row0 + 32 * p) * GPAD + q * 4];
                e[0] = f32_tf32(bv[p].x); e[1] = f32_tf32(bv[p].y);
                e[2] = f32_tf32(bv[p].z); e[3] = f32_tf32(bv[p].w);
            }
        }
    }

    // epilogue
#pragma unroll
    for (int mt = 0; mt < 4; mt++) {
#pragma unroll
        for (int nt = 0; nt < 4; nt++) {
            int row = m0 + mbase + mt * 16 + lr;
            int col = n0 + nbase + nt * 8 + 2 * lc;
            if (OUT_HALF) {
                __half* Ch = (__half*)Cout;
                *(__half2*)(Ch + (size_t)row * N + col) =
                    __floats2half2_rn(c[mt][nt][0] * alpha, c[mt][nt][1] * alpha);
                *(__half2*)(Ch + (size_t)(row + 8) * N + col) =
                    __floats2half2_rn(c[mt][nt][2] * alpha, c[mt][nt][3] * alpha);
            } else {
                float* Cf = (float*)Cout;
                float b0 = bias ? bias[col] : 0.f;
                float b1 = bias ? bias[col + 1] : 0.f;
                float2 f0 = make_float2(c[mt][nt][0] * alpha + b0,
                                        c[mt][nt][1] * alpha + b1);
                float2 f1 = make_float2(c[mt][nt][2] * alpha + b0,
                                        c[mt][nt][3] * alpha + b1);
                *(float2*)(Cf + (size_t)row * N + col) = f0;
                *(float2*)(Cf + (size_t)(row + 8) * N + col) = f1;
            }
        }
    }
}

// ===========================================================================
// Flash attention, fp16 mma (m16n8k16), fp32 softmax/accum. V == K tile.
// BM=64 (4 warps x 16 rows), BN=64 keys/iter, D=64. cp.async K double-buffer.
// ===========================================================================
#define KPAD 72

__global__ __launch_bounds__(128, 3) void flash_mma(
    const __half* __restrict__ Q, const __half* __restrict__ K,
    float* __restrict__ O)
{
    __shared__ __align__(16) __half Qs[64][KPAD];
    __shared__ __align__(16) __half Ks[2][64][KPAD];

    const int tid  = threadIdx.x;
    const int lane = tid & 31;
    const int wid  = tid >> 5;
    const int b  = blockIdx.y >> 4;
    const int h  = blockIdx.y & 15;
    const int q0 = blockIdx.x * 64;

    const __half* Qg = Q + ((size_t)(b * SEQ_N + q0)) * DIM_C + h * HEAD_D;
    const __half* Kg = K + ((size_t)(b * SEQ_M)) * DIM_C + h * HEAD_D;

    const int row0 = tid >> 3;          // 0..15 (+16p)
    const int c8   = tid & 7;

    // load Q tile 64x64 halves
#pragma unroll
    for (int p = 0; p < 4; p++) {
        int row = row0 + 16 * p;
        *(uint4*)&Qs[row][c8 * 8] =
            *(const uint4*)(Qg + (size_t)row * DIM_C + c8 * 8);
    }
    // prefetch K tile 0 (stage 0)
#pragma unroll
    for (int p = 0; p < 4; p++) {
        int row = row0 + 16 * p;
        cp_async16(smem_u32(&Ks[0][row][c8 * 8]),
                   Kg + (size_t)row * DIM_C + c8 * 8);
    }
    CP_COMMIT();
    __syncthreads();

    // build Q fragments (persist whole loop)
    const int lq  = lane & 7;
    const int l8  = lane & 15;
    const int lr8 = l8 & 7;
    const int lh8 = (l8 >> 3) << 3;       // 0 or 8
    uint32_t qa[4][4];
#pragma unroll
    for (int j = 0; j < 4; j++) {
        int qrow = wid * 16 + lq + ((lane >> 3) & 1) * 8;
        int qcol = j * 16 + ((lane >> 4) << 3);
        uint32_t addr = smem_u32(&Qs[qrow][qcol]);
        LDSM_X4(qa[j][0], qa[j][1], qa[j][2], qa[j][3], addr);
    }

    float oc[8][4];
#pragma unroll
    for (int nt = 0; nt < 8; nt++)
#pragma unroll
        for (int r = 0; r < 4; r++) oc[nt][r] = 0.f;
    float m0 = -1e30f, m1 = -1e30f, l0 = 0.f, l1 = 0.f;

    const int iters = SEQ_M / 64;
    for (int it = 0; it < iters; it++) {
        const int s = it & 1;
        CP_WAIT0();
        __syncthreads();
        if (it + 1 < iters) {
            const __half* Kg2 = Kg + (size_t)((it + 1) * 64) * DIM_C;
#pragma unroll
            for (int p = 0; p < 4; p++) {
                int row = row0 + 16 * p;
                cp_async16(smem_u32(&Ks[s ^ 1][row][c8 * 8]),
                           Kg2 + (size_t)row * DIM_C + c8 * 8);
            }
            CP_COMMIT();
        }

        // ---- S = Q @ K^T  (32 f32 regs: 8 n-tiles x 4)
        float sc[8][4];
#pragma unroll
        for (int nt = 0; nt < 8; nt++)
#pragma unroll
            for (int r = 0; r < 4; r++) sc[nt][r] = 0.f;

#pragma unroll
        for (int j = 0; j < 4; j++) {
#pragma unroll
            for (int nt = 0; nt < 8; nt += 2) {
                // x4: {b of tile nt, b of tile nt+1}; rows = keys, non-trans
                int krow = nt * 8 + lr8 + ((lane >> 4) << 3);  // +8 rows -> tile nt+1
                int kcol = j * 16 + lh8;
                uint32_t addr = smem_u32(&Ks[s][krow][kcol]);
                uint32_t b0, b1, b2, b3;
                LDSM_X4(b0, b1, b2, b3, addr);
                mma_f16(sc[nt],     qa[j][0], qa[j][1], qa[j][2], qa[j][3], b0, b1);
                mma_f16(sc[nt + 1], qa[j][0], qa[j][1], qa[j][2], qa[j][3], b2, b3);
            }
        }

        // ---- online softmax (rows lane/4 and lane/4+8)
        float mx0 = -1e30f, mx1 = -1e30f;
#pragma unroll
        for (int nt = 0; nt < 8; nt++) {
            mx0 = fmaxf(mx0, fmaxf(sc[nt][0], sc[nt][1]));
            mx1 = fmaxf(mx1, fmaxf(sc[nt][2], sc[nt][3]));
        }
        mx0 = fmaxf(mx0, __shfl_xor_sync(0xffffffffu, mx0, 1));
        mx0 = fmaxf(mx0, __shfl_xor_sync(0xffffffffu, mx0, 2));
        mx1 = fmaxf(mx1, __shfl_xor_sync(0xffffffffu, mx1, 1));
        mx1 = fmaxf(mx1, __shfl_xor_sync(0xffffffffu, mx1, 2));
        float mn0 = fmaxf(m0, mx0), mn1 = fmaxf(m1, mx1);
        float corr0 = __expf(m0 - mn0), corr1 = __expf(m1 - mn1);
        m0 = mn0; m1 = mn1;
        float rs0 = 0.f, rs1 = 0.f;
#pragma unroll
        for (int nt = 0; nt < 8; nt++) {
            sc[nt][0] = __expf(sc[nt][0] - mn0); rs0 += sc[nt][0];
            sc[nt][1] = __expf(sc[nt][1] - mn0); rs0 += sc[nt][1];
            sc[nt][2] = __expf(sc[nt][2] - mn1); rs1 += sc[nt][2];
            sc[nt][3] = __expf(sc[nt][3] - mn1); rs1 += sc[nt][3];
        }
        rs0 += __shfl_xor_sync(0xffffffffu, rs0, 1);
        rs0 += __shfl_xor_sync(0xffffffffu, rs0, 2);
        rs1 += __shfl_xor_sync(0xffffffffu, rs1, 1);
        rs1 += __shfl_xor_sync(0xffffffffu, rs1, 2);
        l0 = l0 * corr0 + rs0;
        l1 = l1 * corr1 + rs1;
#pragma unroll
        for (int nt = 0; nt < 8; nt++) {
            oc[nt][0] *= corr0; oc[nt][1] *= corr0;
            oc[nt][2] *= corr1; oc[nt][3] *= corr1;
        }

        // ---- O += P @ V, V tile == K tile (trans ldmatrix)
#pragma unroll
        for (int kk = 0; kk < 4; kk++) {
            __half2 h0 = __floats2half2_rn(sc[2 * kk][0], sc[2 * kk][1]);
            __half2 h1 = __floats2half2_rn(sc[2 * kk][2], sc[2 * kk][3]);
            __half2 h2 = __floats2half2_rn(sc[2 * kk + 1][0], sc[2 * kk + 1][1]);
            __half2 h3 = __floats2half2_rn(sc[2 * kk + 1][2], sc[2 * kk + 1][3]);
            uint32_t pa0 = *(uint32_t*)&h0, pa1 = *(uint32_t*)&h1;
            uint32_t pa2 = *(uint32_t*)&h2, pa3 = *(uint32_t*)&h3;
#pragma unroll
            for (int nt = 0; nt < 8; nt += 2) {
                // x4 trans: m0=(k0-7,nt) m1=(k8-15,nt) m2=(k0-7,nt+1) m3=(k8-15,nt+1)
                int vrow = kk * 16 + lh8 + lr8;
                int vcol = nt * 8 + ((lane >> 4) << 3);    // +8 cols -> tile nt+1
                uint32_t addr = smem_u32(&Ks[s][vrow][vcol]);
                uint32_t b0, b1, b2, b3;
                LDSM_X4T(b0, b1, b2, b3, addr);
                mma_f16(oc[nt],     pa0, pa1, pa2, pa3, b0, b1);
                mma_f16(oc[nt + 1], pa0, pa1, pa2, pa3, b2, b3);
            }
        }
    }

    // ---- write O (fp32), normalized
    float inv0 = 1.f / l0, inv1 = 1.f / l1;
    float* Og = O + ((size_t)(b * SEQ_N + q0 + wid * 16 + (lane >> 2))) * DIM_C
                  + h * HEAD_D;
#pragma unroll
    for (int nt = 0; nt < 8; nt++) {
        int col = nt * 8 + 2 * (lane & 3);
        *(float2*)(Og + col) =
            make_float2(oc[nt][0] * inv0, oc[nt][1] * inv0);
        *(float2*)(Og + (size_t)8 * DIM_C + col) =
            make_float2(oc[nt][2] * inv1, oc[nt][3] * inv1);
    }
}

// ---------------------------------------------------------------------------
extern "C" void kernel_launch(void* const* d_in, const int* in_sizes, int n_in,
                              void* d_out, int out_size)
{
    const float* x      = (const float*)d_in[0];
    const float* ctx    = (const float*)d_in[1];
    const float* W_q    = (const float*)d_in[2];
    const float* W_kv   = (const float*)d_in[3];
    const float* W_proj = (const float*)d_in[4];
    const float* b_proj = (const float*)d_in[5];
    float* out = (float*)d_out;

    __half *Qb, *Kb; float* Ob;
    cudaGetSymbolAddress((void**)&Qb, g_Q);
    cudaGetSymbolAddress((void**)&Kb, g_K);
    cudaGetSymbolAddress((void**)&Ob, g_O);

    const int Mrows = B_SZ * SEQ_N;              // 4096
    dim3 ggrid(DIM_C / 128, Mrows / 128);        // (8, 32)
    const int gsmem = 2 * 2 * 128 * GPAD * (int)sizeof(float);  // 73728

    cudaFuncSetAttribute(gemm_mma<true>,
                         cudaFuncAttributeMaxDynamicSharedMemorySize, gsmem);
    cudaFuncSetAttribute(gemm_mma<false>,
                         cudaFuncAttributeMaxDynamicSharedMemorySize, gsmem);

    // Q = x @ W_q^T * 0.125  -> fp16
    gemm_mma<true><<<ggrid, 256, gsmem>>>(x, W_q, Qb, nullptr,
                                          Mrows, DIM_C, DIM_C, 0.125f);
    // K = context @ W_k^T (first half of W_kv; V == K) -> fp16
    gemm_mma<true><<<ggrid, 256, gsmem>>>(ctx, W_kv, Kb, nullptr,
                                          Mrows, DIM_C, DIM_C, 1.0f);

    flash_mma<<<dim3(SEQ_N / 64, B_SZ * HEADS), 128>>>(Qb, Kb, Ob);

    // out = O @ W_proj^T + b_proj  (fp32 out)
    gemm_mma<false><<<ggrid, 256, gsmem>>>(Ob, W_proj, out, b_proj,
                                           Mrows, DIM_C, DIM_C, 1.0f);
}

// round 4
// speedup vs baseline: 6.8341x; 1.5021x over previous
#include <cuda_runtime.h>
#include <cuda_fp16.h>
#include <cstdint>
#include <cstddef>

#define B_SZ    2
#define SEQ_N   2048
#define SEQ_M   2048
#define DIM_C   1024
#define HEADS   16
#define HEAD_D  64

// fp16 scratch (allocation-free rule: __device__ globals)
__device__ __half g_xh[(size_t)B_SZ * SEQ_N * DIM_C];
__device__ __half g_ch[(size_t)B_SZ * SEQ_M * DIM_C];
__device__ __half g_wq[(size_t)DIM_C * DIM_C];
__device__ __half g_wk[(size_t)DIM_C * DIM_C];
__device__ __half g_wp[(size_t)DIM_C * DIM_C];
__device__ __half g_Q[(size_t)B_SZ * SEQ_N * DIM_C];
__device__ __half g_K[(size_t)B_SZ * SEQ_M * DIM_C];
__device__ __half g_O[(size_t)B_SZ * SEQ_N * DIM_C];

// ===========================================================================
// helpers
// ===========================================================================
__device__ __forceinline__ uint32_t smem_u32(const void* p) {
    uint32_t a;
    asm("{ .reg .u64 t; cvta.to.shared.u64 t, %1; cvt.u32.u64 %0, t; }"
        : "=r"(a) : "l"(p));
    return a;
}
__device__ __forceinline__ float fexp2(float x) {
    float y;
    asm("ex2.approx.f32 %0, %1;" : "=f"(y) : "f"(x));
    return y;
}
__device__ __forceinline__ void mma_f16(float c[4], uint32_t a0, uint32_t a1,
                                        uint32_t a2, uint32_t a3,
                                        uint32_t b0, uint32_t b1) {
    asm volatile(
        "mma.sync.aligned.m16n8k16.row.col.f32.f16.f16.f32 "
        "{%0,%1,%2,%3}, {%4,%5,%6,%7}, {%8,%9}, {%0,%1,%2,%3};"
        : "+f"(c[0]), "+f"(c[1]), "+f"(c[2]), "+f"(c[3])
        : "r"(a0), "r"(a1), "r"(a2), "r"(a3), "r"(b0), "r"(b1));
}
#define LDSM_X4(r0, r1, r2, r3, addr)                                          \
    asm volatile("ldmatrix.sync.aligned.m8n8.x4.shared.b16 {%0,%1,%2,%3}, [%4];" \
                 : "=r"(r0), "=r"(r1), "=r"(r2), "=r"(r3) : "r"(addr))
#define LDSM_X4T(r0, r1, r2, r3, addr)                                         \
    asm volatile("ldmatrix.sync.aligned.m8n8.x4.trans.shared.b16 {%0,%1,%2,%3}, [%4];" \
                 : "=r"(r0), "=r"(r1), "=r"(r2), "=r"(r3) : "r"(addr))
__device__ __forceinline__ void cp_async16(uint32_t dst, const void* src) {
    size_t g = __cvta_generic_to_global(src);
    asm volatile("cp.async.cg.shared.global [%0], [%1], 16;"
                 :: "r"(dst), "l"(g) : "memory");
}
#define CP_COMMIT() asm volatile("cp.async.commit_group;" ::: "memory")
#define CP_WAIT0()  asm volatile("cp.async.wait_group 0;" ::: "memory")
#define CP_WAIT1()  asm volatile("cp.async.wait_group 1;" ::: "memory")

// ===========================================================================
// fp32 -> fp16 bulk conversion of all GEMM operands (one pass)
// ===========================================================================
#define N4_X   1048576   // x:   4,194,304 floats / 4
#define N4_C   1048576   // ctx
#define N4_W   262144    // each 1024x1024 weight / 4
#define N4_TOT (N4_X + N4_C + 3 * N4_W)   // 2,883,584

__global__ __launch_bounds__(256) void convert_all(
    const float* __restrict__ x, const float* __restrict__ ctx,
    const float* __restrict__ wq, const float* __restrict__ wkv,
    const float* __restrict__ wp)
{
    int t = blockIdx.x * blockDim.x + threadIdx.x;
    const float* src; __half* dst; int off;
    if (t < N4_X)                    { src = x;   dst = g_xh; off = t; }
    else if (t < N4_X + N4_C)        { src = ctx; dst = g_ch; off = t - N4_X; }
    else if (t < N4_X + N4_C + N4_W) { src = wq;  dst = g_wq; off = t - N4_X - N4_C; }
    else if (t < N4_X + N4_C + 2 * N4_W) { src = wkv; dst = g_wk; off = t - N4_X - N4_C - N4_W; }
    else                             { src = wp;  dst = g_wp; off = t - N4_X - N4_C - 2 * N4_W; }
    float4 v = ((const float4*)src)[off];
    __half2 h0 = __floats2half2_rn(v.x, v.y);
    __half2 h1 = __floats2half2_rn(v.z, v.w);
    ((uint2*)dst)[off] = make_uint2(*(uint32_t*)&h0, *(uint32_t*)&h1);
}

// ===========================================================================
// fp16 GEMM  C[M,N] = alpha * A[M,K] @ B[N,K]^T (+ bias)
// CTA 128x128, 8 warps (2x4), warp 64x32, BK=64, cp.async 2-stage.
// ===========================================================================
#define HPAD 72

template <bool OUT_HALF>
__global__ __launch_bounds__(256, 2) void gemm_h(
    const __half* __restrict__ A, const __half* __restrict__ B,
    void* __restrict__ Cout, const float* __restrict__ bias,
    int M, int N, int K, float alpha)
{
    extern __shared__ __align__(16) __half smh[];
    __half* As = smh;                    // [2][128][HPAD]
    __half* Bs = smh + 2 * 128 * HPAD;   // [2][128][HPAD]

    const int tid  = threadIdx.x;
    const int lane = tid & 31;
    const int wid  = tid >> 5;
    const int mbase = (wid >> 2) * 64;
    const int nbase = (wid & 3) * 32;
    const int m0 = blockIdx.y * 128, n0 = blockIdx.x * 128;
    const int row0 = tid >> 3, c8 = tid & 7;

    const __half* Ag = A + (size_t)(m0 + row0) * K + c8 * 8;
    const __half* Bg = B + (size_t)(n0 + row0) * K + c8 * 8;

    float c[4][4][4];
#pragma unroll
    for (int mt = 0; mt < 4; mt++)
#pragma unroll
        for (int nt = 0; nt < 4; nt++)
#pragma unroll
            for (int r = 0; r < 4; r++) c[mt][nt][r] = 0.f;

    const int nch = K >> 6;     // BK=64

    // prefetch chunk 0 -> stage 0
#pragma unroll
    for (int p = 0; p < 4; p++) {
        int r = row0 + 32 * p;
        cp_async16(smem_u32(As + (size_t)r * HPAD + c8 * 8),
                   Ag + (size_t)(32 * p) * K);
        cp_async16(smem_u32(Bs + (size_t)r * HPAD + c8 * 8),
                   Bg + (size_t)(32 * p) * K);
    }
    CP_COMMIT();

    for (int i = 0; i < nch; i++) {
        const int s = i & 1;
        if (i + 1 < nch) {
            const __half* Ag2 = Ag + (i + 1) * 64;
            const __half* Bg2 = Bg + (i + 1) * 64;
            __half* Ad = As + (size_t)(s ^ 1) * 128 * HPAD;
            __half* Bd = Bs + (size_t)(s ^ 1) * 128 * HPAD;
#pragma unroll
            for (int p = 0; p < 4; p++) {
                int r = row0 + 32 * p;
                cp_async16(smem_u32(Ad + (size_t)r * HPAD + c8 * 8),
                           Ag2 + (size_t)(32 * p) * K);
                cp_async16(smem_u32(Bd + (size_t)r * HPAD + c8 * 8),
                           Bg2 + (size_t)(32 * p) * K);
            }
            CP_COMMIT();
            CP_WAIT1();
        } else {
            CP_WAIT0();
        }
        __syncthreads();

        const __half* Ab = As + (size_t)s * 128 * HPAD;
        const __half* Bb = Bs + (size_t)s * 128 * HPAD;
        const int l15 = lane & 15;
        const int lh  = (lane >> 4) << 3;
#pragma unroll
        for (int ks = 0; ks < 4; ks++) {
            const int col = ks * 16 + lh;
            uint32_t af[4][4];
#pragma unroll
            for (int mt = 0; mt < 4; mt++) {
                uint32_t addr = smem_u32(Ab + (size_t)(mbase + mt * 16 + l15) * HPAD + col);
                LDSM_X4(af[mt][0], af[mt][1], af[mt][2], af[mt][3], addr);
            }
            uint32_t bf[2][4];
#pragma unroll
            for (int nh = 0; nh < 2; nh++) {
                uint32_t addr = smem_u32(Bb + (size_t)(nbase + nh * 16 + l15) * HPAD + col);
                LDSM_X4(bf[nh][0], bf[nh][1], bf[nh][2], bf[nh][3], addr);
            }
            // x4 non-trans on B rows(n): m0=(n0-7,k0-7) m1=(n8-15,k0-7)
            //                            m2=(n0-7,k8-15) m3=(n8-15,k8-15)
#pragma unroll
            for (int mt = 0; mt < 4; mt++)
#pragma unroll
                for (int nh = 0; nh < 2; nh++) {
                    mma_f16(c[mt][nh * 2],     af[mt][0], af[mt][1], af[mt][2], af[mt][3],
                            bf[nh][0], bf[nh][2]);
                    mma_f16(c[mt][nh * 2 + 1], af[mt][0], af[mt][1], af[mt][2], af[mt][3],
                            bf[nh][1], bf[nh][3]);
                }
        }
        __syncthreads();
    }

    // epilogue
    const int lr = lane >> 2, lc = lane & 3;
#pragma unroll
    for (int mt = 0; mt < 4; mt++) {
#pragma unroll
        for (int nt = 0; nt < 4; nt++) {
            int row = m0 + mbase + mt * 16 + lr;
            int col = n0 + nbase + nt * 8 + 2 * lc;
            if (OUT_HALF) {
                __half* Ch = (__half*)Cout;
                *(__half2*)(Ch + (size_t)row * N + col) =
                    __floats2half2_rn(c[mt][nt][0] * alpha, c[mt][nt][1] * alpha);
                *(__half2*)(Ch + (size_t)(row + 8) * N + col) =
                    __floats2half2_rn(c[mt][nt][2] * alpha, c[mt][nt][3] * alpha);
            } else {
                float* Cf = (float*)Cout;
                float b0 = bias ? bias[col] : 0.f;
                float b1 = bias ? bias[col + 1] : 0.f;
                *(float2*)(Cf + (size_t)row * N + col) =
                    make_float2(c[mt][nt][0] * alpha + b0, c[mt][nt][1] * alpha + b1);
                *(float2*)(Cf + (size_t)(row + 8) * N + col) =
                    make_float2(c[mt][nt][2] * alpha + b0, c[mt][nt][3] * alpha + b1);
            }
        }
    }
}

// ===========================================================================
// Flash attention, fp16 mma, fp32 softmax (base-2: log2e folded into Q).
// V == K tile. BM=64 (4 warps), BN=64, D=64. Writes fp16 O.
// ===========================================================================
#define KPAD 72

__global__ __launch_bounds__(128, 4) void flash_mma(
    const __half* __restrict__ Q, const __half* __restrict__ K,
    __half* __restrict__ O)
{
    __shared__ __align__(16) __half Qs[64][KPAD];
    __shared__ __align__(16) __half Ks[2][64][KPAD];

    const int tid  = threadIdx.x;
    const int lane = tid & 31;
    const int wid  = tid >> 5;
    const int b  = blockIdx.y >> 4;
    const int h  = blockIdx.y & 15;
    const int q0 = blockIdx.x * 64;

    const __half* Qg = Q + ((size_t)(b * SEQ_N + q0)) * DIM_C + h * HEAD_D;
    const __half* Kg = K + ((size_t)(b * SEQ_M)) * DIM_C + h * HEAD_D;

    const int row0 = tid >> 3;
    const int c8   = tid & 7;

#pragma unroll
    for (int p = 0; p < 4; p++) {
        int row = row0 + 16 * p;
        *(uint4*)&Qs[row][c8 * 8] =
            *(const uint4*)(Qg + (size_t)row * DIM_C + c8 * 8);
    }
#pragma unroll
    for (int p = 0; p < 4; p++) {
        int row = row0 + 16 * p;
        cp_async16(smem_u32(&Ks[0][row][c8 * 8]),
                   Kg + (size_t)row * DIM_C + c8 * 8);
    }
    CP_COMMIT();
    __syncthreads();

    const int lq  = lane & 7;
    const int l8  = lane & 15;
    const int lr8 = l8 & 7;
    const int lh8 = (l8 >> 3) << 3;
    uint32_t qa[4][4];
#pragma unroll
    for (int j = 0; j < 4; j++) {
        int qrow = wid * 16 + lq + ((lane >> 3) & 1) * 8;
        int qcol = j * 16 + ((lane >> 4) << 3);
        uint32_t addr = smem_u32(&Qs[qrow][qcol]);
        LDSM_X4(qa[j][0], qa[j][1], qa[j][2], qa[j][3], addr);
    }

    float oc[8][4];
#pragma unroll
    for (int nt = 0; nt < 8; nt++)
#pragma unroll
        for (int r = 0; r < 4; r++) oc[nt][r] = 0.f;
    float m0 = -1e30f, m1 = -1e30f, l0 = 0.f, l1 = 0.f;

    const int iters = SEQ_M / 64;
    for (int it = 0; it < iters; it++) {
        const int s = it & 1;
        CP_WAIT0();
        __syncthreads();
        if (it + 1 < iters) {
            const __half* Kg2 = Kg + (size_t)((it + 1) * 64) * DIM_C;
#pragma unroll
            for (int p = 0; p < 4; p++) {
                int row = row0 + 16 * p;
                cp_async16(smem_u32(&Ks[s ^ 1][row][c8 * 8]),
                           Kg2 + (size_t)row * DIM_C + c8 * 8);
            }
            CP_COMMIT();
        }

        float sc[8][4];
#pragma unroll
        for (int nt = 0; nt < 8; nt++)
#pragma unroll
            for (int r = 0; r < 4; r++) sc[nt][r] = 0.f;

#pragma unroll
        for (int j = 0; j < 4; j++) {
#pragma unroll
            for (int nt = 0; nt < 8; nt += 2) {
                int krow = nt * 8 + lr8 + ((lane >> 4) << 3);
                int kcol = j * 16 + lh8;
                uint32_t addr = smem_u32(&Ks[s][krow][kcol]);
                uint32_t b0, b1, b2, b3;
                LDSM_X4(b0, b1, b2, b3, addr);
                mma_f16(sc[nt],     qa[j][0], qa[j][1], qa[j][2], qa[j][3], b0, b1);
                mma_f16(sc[nt + 1], qa[j][0], qa[j][1], qa[j][2], qa[j][3], b2, b3);
            }
        }

        // online softmax in base-2 (Q pre-scaled by log2e)
        float mx0 = -1e30f, mx1 = -1e30f;
#pragma unroll
        for (int nt = 0; nt < 8; nt++) {
            mx0 = fmaxf(mx0, fmaxf(sc[nt][0], sc[nt][1]));
            mx1 = fmaxf(mx1, fmaxf(sc[nt][2], sc[nt][3]));
        }
        mx0 = fmaxf(mx0, __shfl_xor_sync(0xffffffffu, mx0, 1));
        mx0 = fmaxf(mx0, __shfl_xor_sync(0xffffffffu, mx0, 2));
        mx1 = fmaxf(mx1, __shfl_xor_sync(0xffffffffu, mx1, 1));
        mx1 = fmaxf(mx1, __shfl_xor_sync(0xffffffffu, mx1, 2));
        float mn0 = fmaxf(m0, mx0), mn1 = fmaxf(m1, mx1);
        float corr0 = fexp2(m0 - mn0), corr1 = fexp2(m1 - mn1);
        m0 = mn0; m1 = mn1;
        float rs0 = 0.f, rs1 = 0.f;
#pragma unroll
        for (int nt = 0; nt < 8; nt++) {
            sc[nt][0] = fexp2(sc[nt][0] - mn0); rs0 += sc[nt][0];
            sc[nt][1] = fexp2(sc[nt][1] - mn0); rs0 += sc[nt][1];
            sc[nt][2] = fexp2(sc[nt][2] - mn1); rs1 += sc[nt][2];
            sc[nt][3] = fexp2(sc[nt][3] - mn1); rs1 += sc[nt][3];
        }
        rs0 += __shfl_xor_sync(0xffffffffu, rs0, 1);
        rs0 += __shfl_xor_sync(0xffffffffu, rs0, 2);
        rs1 += __shfl_xor_sync(0xffffffffu, rs1, 1);
        rs1 += __shfl_xor_sync(0xffffffffu, rs1, 2);
        l0 = l0 * corr0 + rs0;
        l1 = l1 * corr1 + rs1;
#pragma unroll
        for (int nt = 0; nt < 8; nt++) {
            oc[nt][0] *= corr0; oc[nt][1] *= corr0;
            oc[nt][2] *= corr1; oc[nt][3] *= corr1;
        }

#pragma unroll
        for (int kk = 0; kk < 4; kk++) {
            __half2 h0 = __floats2half2_rn(sc[2 * kk][0], sc[2 * kk][1]);
            __half2 h1 = __floats2half2_rn(sc[2 * kk][2], sc[2 * kk][3]);
            __half2 h2 = __floats2half2_rn(sc[2 * kk + 1][0], sc[2 * kk + 1][1]);
            __half2 h3 = __floats2half2_rn(sc[2 * kk + 1][2], sc[2 * kk + 1][3]);
            uint32_t pa0 = *(uint32_t*)&h0, pa1 = *(uint32_t*)&h1;
            uint32_t pa2 = *(uint32_t*)&h2, pa3 = *(uint32_t*)&h3;
#pragma unroll
            for (int nt = 0; nt < 8; nt += 2) {
                int vrow = kk * 16 + lh8 + lr8;
                int vcol = nt * 8 + ((lane >> 4) << 3);
                uint32_t addr = smem_u32(&Ks[s][vrow][vcol]);
                uint32_t b0, b1, b2, b3;
                LDSM_X4T(b0, b1, b2, b3, addr);
                mma_f16(oc[nt],     pa0, pa1, pa2, pa3, b0, b1);
                mma_f16(oc[nt + 1], pa0, pa1, pa2, pa3, b2, b3);
            }
        }
    }

    float inv0 = 1.f / l0, inv1 = 1.f / l1;
    __half* Og = O + ((size_t)(b * SEQ_N + q0 + wid * 16 + (lane >> 2))) * DIM_C
                   + h * HEAD_D;
#pragma unroll
    for (int nt = 0; nt < 8; nt++) {
        int col = nt * 8 + 2 * (lane & 3);
        *(__half2*)(Og + col) =
            __floats2half2_rn(oc[nt][0] * inv0, oc[nt][1] * inv0);
        *(__half2*)(Og + (size_t)8 * DIM_C + col) =
            __floats2half2_rn(oc[nt][2] * inv1, oc[nt][3] * inv1);
    }
}

// ---------------------------------------------------------------------------
extern "C" void kernel_launch(void* const* d_in, const int* in_sizes, int n_in,
                              void* d_out, int out_size)
{
    const float* x      = (const float*)d_in[0];
    const float* ctx    = (const float*)d_in[1];
    const float* W_q    = (const float*)d_in[2];
    const float* W_kv   = (const float*)d_in[3];
    const float* W_proj = (const float*)d_in[4];
    const float* b_proj = (const float*)d_in[5];
    float* out = (float*)d_out;

    __half *xh, *ch, *wq, *wk, *wp, *Qb, *Kb, *Ob;
    cudaGetSymbolAddress((void**)&xh, g_xh);
    cudaGetSymbolAddress((void**)&ch, g_ch);
    cudaGetSymbolAddress((void**)&wq, g_wq);
    cudaGetSymbolAddress((void**)&wk, g_wk);
    cudaGetSymbolAddress((void**)&wp, g_wp);
    cudaGetSymbolAddress((void**)&Qb, g_Q);
    cudaGetSymbolAddress((void**)&Kb, g_K);
    cudaGetSymbolAddress((void**)&Ob, g_O);

    convert_all<<<N4_TOT / 256, 256>>>(x, ctx, W_q, W_kv, W_proj);

    const int Mrows = B_SZ * SEQ_N;              // 4096
    dim3 ggrid(DIM_C / 128, Mrows / 128);        // (8, 32)
    const int gsmem = 2 * 2 * 128 * HPAD * (int)sizeof(__half);  // 73728

    cudaFuncSetAttribute(gemm_h<true>,
                         cudaFuncAttributeMaxDynamicSharedMemorySize, gsmem);
    cudaFuncSetAttribute(gemm_h<false>,
                         cudaFuncAttributeMaxDynamicSharedMemorySize, gsmem);

    // Q = x @ W_q^T * (0.125 * log2e)  -> fp16 (base-2 softmax downstream)
    gemm_h<true><<<ggrid, 256, gsmem>>>(xh, wq, Qb, nullptr,
                                        Mrows, DIM_C, DIM_C,
                                        0.125f * 1.44269504f);
    // K = context @ W_k^T -> fp16  (V == K)
    gemm_h<true><<<ggrid, 256, gsmem>>>(ch, wk, Kb, nullptr,
                                        Mrows, DIM_C, DIM_C, 1.0f);

    flash_mma<<<dim3(SEQ_N / 64, B_SZ * HEADS), 128>>>(Qb, Kb, Ob);

    // out = O @ W_proj^T + b_proj  (fp32 out)
    gemm_h<false><<<ggrid, 256, gsmem>>>(Ob, wp, out, b_proj,
                                         Mrows, DIM_C, DIM_C, 1.0f);
}

// round 5
// speedup vs baseline: 7.2043x; 1.0542x over previous
#include <cuda_runtime.h>
#include <cuda_fp16.h>
#include <cstdint>
#include <cstddef>

#define B_SZ    2
#define SEQ_N   2048
#define SEQ_M   2048
#define DIM_C   1024
#define HEADS   16
#define HEAD_D  64

// fp16 scratch (allocation-free rule: __device__ globals)
__device__ __half g_xh[(size_t)B_SZ * SEQ_N * DIM_C];
__device__ __half g_ch[(size_t)B_SZ * SEQ_M * DIM_C];
__device__ __half g_wq[(size_t)DIM_C * DIM_C];
__device__ __half g_wk[(size_t)DIM_C * DIM_C];
__device__ __half g_wp[(size_t)DIM_C * DIM_C];
__device__ __half g_Q[(size_t)B_SZ * SEQ_N * DIM_C];
__device__ __half g_K[(size_t)B_SZ * SEQ_M * DIM_C];
__device__ __half g_O[(size_t)B_SZ * SEQ_N * DIM_C];

// ===========================================================================
// helpers
// ===========================================================================
__device__ __forceinline__ uint32_t smem_u32(const void* p) {
    uint32_t a;
    asm("{ .reg .u64 t; cvta.to.shared.u64 t, %1; cvt.u32.u64 %0, t; }"
        : "=r"(a) : "l"(p));
    return a;
}
__device__ __forceinline__ float fexp2(float x) {
    float y;
    asm("ex2.approx.f32 %0, %1;" : "=f"(y) : "f"(x));
    return y;
}
__device__ __forceinline__ uint32_t hexp2x2(uint32_t x) {
    uint32_t y;
    asm("ex2.approx.f16x2 %0, %1;" : "=r"(y) : "r"(x));
    return y;
}
__device__ __forceinline__ void mma_f16(float c[4], uint32_t a0, uint32_t a1,
                                        uint32_t a2, uint32_t a3,
                                        uint32_t b0, uint32_t b1) {
    asm volatile(
        "mma.sync.aligned.m16n8k16.row.col.f32.f16.f16.f32 "
        "{%0,%1,%2,%3}, {%4,%5,%6,%7}, {%8,%9}, {%0,%1,%2,%3};"
        : "+f"(c[0]), "+f"(c[1]), "+f"(c[2]), "+f"(c[3])
        : "r"(a0), "r"(a1), "r"(a2), "r"(a3), "r"(b0), "r"(b1));
}
#define LDSM_X4(r0, r1, r2, r3, addr)                                          \
    asm volatile("ldmatrix.sync.aligned.m8n8.x4.shared.b16 {%0,%1,%2,%3}, [%4];" \
                 : "=r"(r0), "=r"(r1), "=r"(r2), "=r"(r3) : "r"(addr))
#define LDSM_X4T(r0, r1, r2, r3, addr)                                         \
    asm volatile("ldmatrix.sync.aligned.m8n8.x4.trans.shared.b16 {%0,%1,%2,%3}, [%4];" \
                 : "=r"(r0), "=r"(r1), "=r"(r2), "=r"(r3) : "r"(addr))
__device__ __forceinline__ void cp_async16(uint32_t dst, const void* src) {
    size_t g = __cvta_generic_to_global(src);
    asm volatile("cp.async.cg.shared.global [%0], [%1], 16;"
                 :: "r"(dst), "l"(g) : "memory");
}
#define CP_COMMIT() asm volatile("cp.async.commit_group;" ::: "memory")
#define CP_WAIT0()  asm volatile("cp.async.wait_group 0;" ::: "memory")
#define CP_WAIT1()  asm volatile("cp.async.wait_group 1;" ::: "memory")

// ===========================================================================
// fp32 -> fp16 bulk conversion of all GEMM operands (one pass)
// ===========================================================================
#define N4_X   1048576
#define N4_C   1048576
#define N4_W   262144
#define N4_TOT (N4_X + N4_C + 3 * N4_W)

__global__ __launch_bounds__(256) void convert_all(
    const float* __restrict__ x, const float* __restrict__ ctx,
    const float* __restrict__ wq, const float* __restrict__ wkv,
    const float* __restrict__ wp)
{
    int t = blockIdx.x * blockDim.x + threadIdx.x;
    const float* src; __half* dst; int off;
    if (t < N4_X)                    { src = x;   dst = g_xh; off = t; }
    else if (t < N4_X + N4_C)        { src = ctx; dst = g_ch; off = t - N4_X; }
    else if (t < N4_X + N4_C + N4_W) { src = wq;  dst = g_wq; off = t - N4_X - N4_C; }
    else if (t < N4_X + N4_C + 2 * N4_W) { src = wkv; dst = g_wk; off = t - N4_X - N4_C - N4_W; }
    else                             { src = wp;  dst = g_wp; off = t - N4_X - N4_C - 2 * N4_W; }
    float4 v = ((const float4*)src)[off];
    __half2 h0 = __floats2half2_rn(v.x, v.y);
    __half2 h1 = __floats2half2_rn(v.z, v.w);
    ((uint2*)dst)[off] = make_uint2(*(uint32_t*)&h0, *(uint32_t*)&h1);
}

// ===========================================================================
// fp16 GEMM  C[M,N] = alpha * A[M,K] @ B[N,K]^T (+ bias)
// CTA 128x128, 4 warps (2x2), warp tile 64x64, BK=64, 3-stage cp.async ring.
// ===========================================================================
#define HPAD   72
#define GSTAGE (2 * 128 * HPAD)           // halves per stage (A then B)

template <bool OUT_HALF>
__global__ __launch_bounds__(128, 2) void gemm_h(
    const __half* __restrict__ A, const __half* __restrict__ B,
    void* __restrict__ Cout, const float* __restrict__ bias,
    int M, int N, int K, float alpha)
{
    extern __shared__ __align__(16) __half smh[];

    const int tid  = threadIdx.x;
    const int lane = tid & 31;
    const int wid  = tid >> 5;
    const int wm   = (wid >> 1) * 64;
    const int wn   = (wid & 1) * 64;
    const int m0 = blockIdx.y * 128, n0 = blockIdx.x * 128;
    const int row0 = tid >> 3, c8 = tid & 7;

    const __half* Ag = A + (size_t)(m0 + row0) * K + c8 * 8;
    const __half* Bg = B + (size_t)(n0 + row0) * K + c8 * 8;

    float c[4][8][4];
#pragma unroll
    for (int mt = 0; mt < 4; mt++)
#pragma unroll
        for (int nt = 0; nt < 8; nt++)
#pragma unroll
            for (int r = 0; r < 4; r++) c[mt][nt][r] = 0.f;

    const int nch = K >> 6;

    auto issue = [&](int i) {
        const int st = i % 3;
        __half* Ad = smh + (size_t)st * GSTAGE;
        __half* Bd = Ad + 128 * HPAD;
        const __half* Ags = Ag + i * 64;
        const __half* Bgs = Bg + i * 64;
#pragma unroll
        for (int p = 0; p < 8; p++) {
            int r = row0 + 16 * p;
            cp_async16(smem_u32(Ad + (size_t)r * HPAD + c8 * 8),
                       Ags + (size_t)(16 * p) * K);
            cp_async16(smem_u32(Bd + (size_t)r * HPAD + c8 * 8),
                       Bgs + (size_t)(16 * p) * K);
        }
    };

    issue(0); CP_COMMIT();
    issue(1); CP_COMMIT();

    const int l15 = lane & 15;
    const int lh  = (lane >> 4) << 3;

    for (int i = 0; i < nch; i++) {
        CP_WAIT1();
        __syncthreads();
        if (i + 2 < nch) issue(i + 2);
        CP_COMMIT();                       // empty commit keeps groups uniform

        const int st = i % 3;
        const __half* Ab = smh + (size_t)st * GSTAGE;
        const __half* Bb = Ab + 128 * HPAD;
#pragma unroll
        for (int ks = 0; ks < 4; ks++) {
            const int col = ks * 16 + lh;
            uint32_t af[4][4];
#pragma unroll
            for (int mt = 0; mt < 4; mt++) {
                uint32_t addr = smem_u32(Ab + (size_t)(wm + mt * 16 + l15) * HPAD + col);
                LDSM_X4(af[mt][0], af[mt][1], af[mt][2], af[mt][3], addr);
            }
            uint32_t bf[4][4];
#pragma unroll
            for (int nh = 0; nh < 4; nh++) {
                uint32_t addr = smem_u32(Bb + (size_t)(wn + nh * 16 + l15) * HPAD + col);
                LDSM_X4(bf[nh][0], bf[nh][1], bf[nh][2], bf[nh][3], addr);
            }
#pragma unroll
            for (int mt = 0; mt < 4; mt++)
#pragma unroll
                for (int nh = 0; nh < 4; nh++) {
                    mma_f16(c[mt][nh * 2],     af[mt][0], af[mt][1], af[mt][2], af[mt][3],
                            bf[nh][0], bf[nh][2]);
                    mma_f16(c[mt][nh * 2 + 1], af[mt][0], af[mt][1], af[mt][2], af[mt][3],
                            bf[nh][1], bf[nh][3]);
                }
        }
    }

    // epilogue
    const int lr = lane >> 2, lc = lane & 3;
#pragma unroll
    for (int mt = 0; mt < 4; mt++) {
#pragma unroll
        for (int nt = 0; nt < 8; nt++) {
            int row = m0 + wm + mt * 16 + lr;
            int col = n0 + wn + nt * 8 + 2 * lc;
            if (OUT_HALF) {
                __half* Ch = (__half*)Cout;
                *(__half2*)(Ch + (size_t)row * N + col) =
                    __floats2half2_rn(c[mt][nt][0] * alpha, c[mt][nt][1] * alpha);
                *(__half2*)(Ch + (size_t)(row + 8) * N + col) =
                    __floats2half2_rn(c[mt][nt][2] * alpha, c[mt][nt][3] * alpha);
            } else {
                float* Cf = (float*)Cout;
                float b0 = bias ? bias[col] : 0.f;
                float b1 = bias ? bias[col + 1] : 0.f;
                *(float2*)(Cf + (size_t)row * N + col) =
                    make_float2(c[mt][nt][0] * alpha + b0, c[mt][nt][1] * alpha + b1);
                *(float2*)(Cf + (size_t)(row + 8) * N + col) =
                    make_float2(c[mt][nt][2] * alpha + b0, c[mt][nt][3] * alpha + b1);
            }
        }
    }
}

// ===========================================================================
// Flash attention, fp16 mma, base-2 softmax. V == K tile.
// l via ones-column MMA; exp via ex2.approx.f16x2 on packed P.
// ===========================================================================
#define KPAD 72

__global__ __launch_bounds__(128, 4) void flash_mma(
    const __half* __restrict__ Q, const __half* __restrict__ K,
    __half* __restrict__ O)
{
    __shared__ __align__(16) __half Qs[64][KPAD];
    __shared__ __align__(16) __half Ks[2][64][KPAD];

    const int tid  = threadIdx.x;
    const int lane = tid & 31;
    const int wid  = tid >> 5;
    const int b  = blockIdx.y >> 4;
    const int h  = blockIdx.y & 15;
    const int q0 = blockIdx.x * 64;

    const __half* Qg = Q + ((size_t)(b * SEQ_N + q0)) * DIM_C + h * HEAD_D;
    const __half* Kg = K + ((size_t)(b * SEQ_M)) * DIM_C + h * HEAD_D;

    const int row0 = tid >> 3;
    const int c8   = tid & 7;

#pragma unroll
    for (int p = 0; p < 4; p++) {
        int row = row0 + 16 * p;
        *(uint4*)&Qs[row][c8 * 8] =
            *(const uint4*)(Qg + (size_t)row * DIM_C + c8 * 8);
    }
#pragma unroll
    for (int p = 0; p < 4; p++) {
        int row = row0 + 16 * p;
        cp_async16(smem_u32(&Ks[0][row][c8 * 8]),
                   Kg + (size_t)row * DIM_C + c8 * 8);
    }
    CP_COMMIT();
    __syncthreads();

    const int lq  = lane & 7;
    const int l8  = lane & 15;
    const int lr8 = l8 & 7;
    const int lh8 = (l8 >> 3) << 3;
    uint32_t qa[4][4];
#pragma unroll
    for (int j = 0; j < 4; j++) {
        int qrow = wid * 16 + lq + ((lane >> 3) & 1) * 8;
        int qcol = j * 16 + ((lane >> 4) << 3);
        uint32_t addr = smem_u32(&Qs[qrow][qcol]);
        LDSM_X4(qa[j][0], qa[j][1], qa[j][2], qa[j][3], addr);
    }

    float oc[8][4], lacc[4];
#pragma unroll
    for (int nt = 0; nt < 8; nt++)
#pragma unroll
        for (int r = 0; r < 4; r++) oc[nt][r] = 0.f;
#pragma unroll
    for (int r = 0; r < 4; r++) lacc[r] = 0.f;
    float m0 = -1e30f, m1 = -1e30f;
    const uint32_t ONES = 0x3C003C00u;

    const int iters = SEQ_M / 64;
    for (int it = 0; it < iters; it++) {
        const int s = it & 1;
        CP_WAIT0();
        __syncthreads();
        if (it + 1 < iters) {
            const __half* Kg2 = Kg + (size_t)((it + 1) * 64) * DIM_C;
#pragma unroll
            for (int p = 0; p < 4; p++) {
                int row = row0 + 16 * p;
                cp_async16(smem_u32(&Ks[s ^ 1][row][c8 * 8]),
                           Kg2 + (size_t)row * DIM_C + c8 * 8);
            }
            CP_COMMIT();
        }

        // ---- S = Q @ K^T
        float sc[8][4];
#pragma unroll
        for (int nt = 0; nt < 8; nt++)
#pragma unroll
            for (int r = 0; r < 4; r++) sc[nt][r] = 0.f;

#pragma unroll
        for (int j = 0; j < 4; j++) {
#pragma unroll
            for (int nt = 0; nt < 8; nt += 2) {
                int krow = nt * 8 + lr8 + ((lane >> 4) << 3);
                int kcol = j * 16 + lh8;
                uint32_t addr = smem_u32(&Ks[s][krow][kcol]);
                uint32_t b0, b1, b2, b3;
                LDSM_X4(b0, b1, b2, b3, addr);
                mma_f16(sc[nt],     qa[j][0], qa[j][1], qa[j][2], qa[j][3], b0, b1);
                mma_f16(sc[nt + 1], qa[j][0], qa[j][1], qa[j][2], qa[j][3], b2, b3);
            }
        }

        // ---- max + rescale
        float mx0 = -1e30f, mx1 = -1e30f;
#pragma unroll
        for (int nt = 0; nt < 8; nt++) {
            mx0 = fmaxf(mx0, fmaxf(sc[nt][0], sc[nt][1]));
            mx1 = fmaxf(mx1, fmaxf(sc[nt][2], sc[nt][3]));
        }
        mx0 = fmaxf(mx0, __shfl_xor_sync(0xffffffffu, mx0, 1));
        mx0 = fmaxf(mx0, __shfl_xor_sync(0xffffffffu, mx0, 2));
        mx1 = fmaxf(mx1, __shfl_xor_sync(0xffffffffu, mx1, 1));
        mx1 = fmaxf(mx1, __shfl_xor_sync(0xffffffffu, mx1, 2));
        float mn0 = fmaxf(m0, mx0), mn1 = fmaxf(m1, mx1);
        float corr0 = fexp2(m0 - mn0), corr1 = fexp2(m1 - mn1);
        m0 = mn0; m1 = mn1;
#pragma unroll
        for (int nt = 0; nt < 8; nt++) {
            oc[nt][0] *= corr0; oc[nt][1] *= corr0;
            oc[nt][2] *= corr1; oc[nt][3] *= corr1;
        }
        lacc[0] *= corr0; lacc[1] *= corr0;
        lacc[2] *= corr1; lacc[3] *= corr1;

        // ---- P = exp2(S - m) packed to fp16 (sub in fp32, ex2 in f16x2)
        uint32_t pA[8], pB[8];
#pragma unroll
        for (int nt = 0; nt < 8; nt++) {
            __half2 h0 = __floats2half2_rn(sc[nt][0] - mn0, sc[nt][1] - mn0);
            __half2 h1 = __floats2half2_rn(sc[nt][2] - mn1, sc[nt][3] - mn1);
            pA[nt] = hexp2x2(*(uint32_t*)&h0);
            pB[nt] = hexp2x2(*(uint32_t*)&h1);
        }

        // ---- l += P @ ones   (row-sum rides a 4-reg accumulator)
#pragma unroll
        for (int kk = 0; kk < 4; kk++)
            mma_f16(lacc, pA[2 * kk], pB[2 * kk], pA[2 * kk + 1], pB[2 * kk + 1],
                    ONES, ONES);

        // ---- O += P @ V, V tile == K tile (trans ldmatrix)
#pragma unroll
        for (int kk = 0; kk < 4; kk++) {
            uint32_t pa0 = pA[2 * kk], pa1 = pB[2 * kk];
            uint32_t pa2 = pA[2 * kk + 1], pa3 = pB[2 * kk + 1];
#pragma unroll
            for (int nt = 0; nt < 8; nt += 2) {
                int vrow = kk * 16 + lh8 + lr8;
                int vcol = nt * 8 + ((lane >> 4) << 3);
                uint32_t addr = smem_u32(&Ks[s][vrow][vcol]);
                uint32_t b0, b1, b2, b3;
                LDSM_X4T(b0, b1, b2, b3, addr);
                mma_f16(oc[nt],     pa0, pa1, pa2, pa3, b0, b1);
                mma_f16(oc[nt + 1], pa0, pa1, pa2, pa3, b2, b3);
            }
        }
    }

    float inv0 = 1.f / lacc[0], inv1 = 1.f / lacc[2];
    __half* Og = O + ((size_t)(b * SEQ_N + q0 + wid * 16 + (lane >> 2))) * DIM_C
                   + h * HEAD_D;
#pragma unroll
    for (int nt = 0; nt < 8; nt++) {
        int col = nt * 8 + 2 * (lane & 3);
        *(__half2*)(Og + col) =
            __floats2half2_rn(oc[nt][0] * inv0, oc[nt][1] * inv0);
        *(__half2*)(Og + (size_t)8 * DIM_C + col) =
            __floats2half2_rn(oc[nt][2] * inv1, oc[nt][3] * inv1);
    }
}

// ---------------------------------------------------------------------------
extern "C" void kernel_launch(void* const* d_in, const int* in_sizes, int n_in,
                              void* d_out, int out_size)
{
    const float* x      = (const float*)d_in[0];
    const float* ctx    = (const float*)d_in[1];
    const float* W_q    = (const float*)d_in[2];
    const float* W_kv   = (const float*)d_in[3];
    const float* W_proj = (const float*)d_in[4];
    const float* b_proj = (const float*)d_in[5];
    float* out = (float*)d_out;

    __half *xh, *ch, *wq, *wk, *wp, *Qb, *Kb, *Ob;
    cudaGetSymbolAddress((void**)&xh, g_xh);
    cudaGetSymbolAddress((void**)&ch, g_ch);
    cudaGetSymbolAddress((void**)&wq, g_wq);
    cudaGetSymbolAddress((void**)&wk, g_wk);
    cudaGetSymbolAddress((void**)&wp, g_wp);
    cudaGetSymbolAddress((void**)&Qb, g_Q);
    cudaGetSymbolAddress((void**)&Kb, g_K);
    cudaGetSymbolAddress((void**)&Ob, g_O);

    convert_all<<<N4_TOT / 256, 256>>>(x, ctx, W_q, W_kv, W_proj);

    const int Mrows = B_SZ * SEQ_N;              // 4096
    dim3 ggrid(DIM_C / 128, Mrows / 128);        // (8, 32)
    const int gsmem = 3 * GSTAGE * (int)sizeof(__half);  // 110592

    cudaFuncSetAttribute(gemm_h<true>,
                         cudaFuncAttributeMaxDynamicSharedMemorySize, gsmem);
    cudaFuncSetAttribute(gemm_h<false>,
                         cudaFuncAttributeMaxDynamicSharedMemorySize, gsmem);

    // Q = x @ W_q^T * (0.125 * log2e)  -> fp16 (base-2 softmax downstream)
    gemm_h<true><<<ggrid, 128, gsmem>>>(xh, wq, Qb, nullptr,
                                        Mrows, DIM_C, DIM_C,
                                        0.125f * 1.44269504f);
    // K = context @ W_k^T -> fp16  (V == K)
    gemm_h<true><<<ggrid, 128, gsmem>>>(ch, wk, Kb, nullptr,
                                        Mrows, DIM_C, DIM_C, 1.0f);

    flash_mma<<<dim3(SEQ_N / 64, B_SZ * HEADS), 128>>>(Qb, Kb, Ob);

    // out = O @ W_proj^T + b_proj  (fp32 out)
    gemm_h<false><<<ggrid, 128, gsmem>>>(Ob, wp, out, b_proj,
                                         Mrows, DIM_C, DIM_C, 1.0f);
}